// round 2
// baseline (speedup 1.0000x reference)
#include <cuda_runtime.h>
#include <cuda_bf16.h>

#define N_NODES 100000
#define N_EDGES 1600000
#define FEAT 128
#define NCLS 47

// ---------------- scratch (no allocation allowed) ----------------
__device__ __align__(16) float g_h0[N_NODES * FEAT];
__device__ __align__(16) float g_h1[N_NODES * FEAT];
__device__ __align__(16) float g_agg[N_NODES * FEAT];
__device__ __align__(16) float g_deg[N_NODES];
__device__ __align__(16) float g_inv[N_NODES];

// ---------------- packed f32x2 helpers ----------------
__device__ __forceinline__ unsigned long long pack2(float x, float y) {
    unsigned long long r;
    asm("mov.b64 %0, {%1, %2};" : "=l"(r) : "f"(x), "f"(y));
    return r;
}
__device__ __forceinline__ unsigned long long dup2(float x) {
    unsigned long long r;
    asm("mov.b64 %0, {%1, %1};" : "=l"(r) : "f"(x));
    return r;
}
__device__ __forceinline__ void unpack2(unsigned long long v, float& x, float& y) {
    asm("mov.b64 {%0, %1}, %2;" : "=f"(x), "=f"(y) : "l"(v));
}
__device__ __forceinline__ unsigned long long fma2(unsigned long long a,
                                                   unsigned long long b,
                                                   unsigned long long c) {
    unsigned long long d;
    asm("fma.rn.f32x2 %0, %1, %2, %3;" : "=l"(d) : "l"(a), "l"(b), "l"(c));
    return d;
}
__device__ __forceinline__ void red_add_v4(float* addr, float4 v) {
    asm volatile("red.global.add.v4.f32 [%0], {%1, %2, %3, %4};"
                 :: "l"(addr), "f"(v.x), "f"(v.y), "f"(v.z), "f"(v.w)
                 : "memory");
}

// ---------------- small kernels ----------------
__global__ void zero_f4(float4* p, int n4) {
    int i = blockIdx.x * blockDim.x + threadIdx.x;
    if (i < n4) p[i] = make_float4(0.f, 0.f, 0.f, 0.f);
}

__global__ void deg_kernel(const int* __restrict__ dst, float* __restrict__ deg) {
    int e = blockIdx.x * blockDim.x + threadIdx.x;
    if (e < N_EDGES) atomicAdd(&deg[dst[e]], 1.0f);
}

__global__ void invdeg_kernel(const float* __restrict__ deg, float* __restrict__ inv) {
    int i = blockIdx.x * blockDim.x + threadIdx.x;
    if (i < N_NODES) inv[i] = 1.0f / fmaxf(deg[i], 1.0f);
}

__global__ void gather_kernel(const float* __restrict__ embed,
                              const int* __restrict__ nodes,
                              float* __restrict__ h0) {
    int t = blockIdx.x * blockDim.x + threadIdx.x;
    int v = t >> 5, l = t & 31;
    if (v < N_NODES) {
        int s = nodes[v];
        reinterpret_cast<float4*>(h0)[v * 32 + l] =
            reinterpret_cast<const float4*>(embed)[s * 32 + l];
    }
}

// warp per edge: 32 lanes x float4 = 128 floats, fully coalesced gather,
// vectorized 16B reductions into agg.
__global__ void scatter_kernel(const float* __restrict__ h,
                               const int* __restrict__ src,
                               const int* __restrict__ dst,
                               float* __restrict__ agg) {
    int t = blockIdx.x * blockDim.x + threadIdx.x;
    int e = t >> 5, l = t & 31;
    if (e < N_EDGES) {
        int s = src[e];
        int d = dst[e];
        float4 v = reinterpret_cast<const float4*>(h)[s * 32 + l];
        red_add_v4(&agg[d * 128 + l * 4], v);
    }
}

// ---------------- fused dual GEMM ----------------
// out[v,:] = (agg[v]*inv[v]) @ Wn + h[v] @ Ws + b    (optionally ReLU)
// K = 256 (concat of mean part and self part), BM=128, BN=128, BK=16,
// 256 threads, 8x8 micro-tile, FFMA2-packed over row pairs.
template <int NOUT, bool RELU>
__global__ void __launch_bounds__(256) gemm_kernel(
    const float* __restrict__ h, const float* __restrict__ agg,
    const float* __restrict__ inv, const float* __restrict__ Wn,
    const float* __restrict__ Ws, const float* __restrict__ bias,
    float* __restrict__ out) {
    __shared__ float As[16][132];   // [k][m], padded
    __shared__ float Bs[16][128];   // [k][n]

    const int tid = threadIdx.x;
    const int r0 = blockIdx.x * 128;
    const int tx = tid & 15;   // col group (8 cols)
    const int ty = tid >> 4;   // row group (8 rows)

    unsigned long long acc[4][8];
#pragma unroll
    for (int i = 0; i < 4; i++)
#pragma unroll
        for (int j = 0; j < 8; j++) acc[i][j] = 0ull;

    for (int k0 = 0; k0 < 256; k0 += 16) {
        // ---- load A tile (128 rows x 16 k), assembled from agg/h ----
#pragma unroll
        for (int p = 0; p < 2; p++) {
            int idx4 = tid + p * 256;
            int m = idx4 >> 2;
            int kl = (idx4 & 3) * 4;
            int row = r0 + m;
            float4 v = make_float4(0.f, 0.f, 0.f, 0.f);
            if (row < N_NODES) {
                int kg = k0 + kl;
                if (kg < 128) {
                    v = reinterpret_cast<const float4*>(agg)[row * 32 + (kg >> 2)];
                    float id = inv[row];
                    v.x *= id; v.y *= id; v.z *= id; v.w *= id;
                } else {
                    v = reinterpret_cast<const float4*>(h)[row * 32 + ((kg - 128) >> 2)];
                }
            }
            As[kl + 0][m] = v.x;
            As[kl + 1][m] = v.y;
            As[kl + 2][m] = v.z;
            As[kl + 3][m] = v.w;
        }
        // ---- load B tile (16 k x 128 n) from Wn/Ws ----
#pragma unroll
        for (int p = 0; p < 8; p++) {
            int idx = tid + p * 256;
            int k = idx >> 7;
            int n = idx & 127;
            int kg = k0 + k;
            float w = 0.f;
            if (n < NOUT)
                w = (kg < 128) ? Wn[kg * NOUT + n] : Ws[(kg - 128) * NOUT + n];
            Bs[k][n] = w;
        }
        __syncthreads();

#pragma unroll
        for (int kk = 0; kk < 16; kk++) {
            const float2* a2p = reinterpret_cast<const float2*>(&As[kk][ty * 8]);
            unsigned long long a2[4];
#pragma unroll
            for (int i = 0; i < 4; i++) {
                float2 t = a2p[i];
                a2[i] = pack2(t.x, t.y);
            }
            const float4* b4p = reinterpret_cast<const float4*>(&Bs[kk][tx * 8]);
            float4 bA = b4p[0];
            float4 bB = b4p[1];
            unsigned long long bd[8];
            bd[0] = dup2(bA.x); bd[1] = dup2(bA.y); bd[2] = dup2(bA.z); bd[3] = dup2(bA.w);
            bd[4] = dup2(bB.x); bd[5] = dup2(bB.y); bd[6] = dup2(bB.z); bd[7] = dup2(bB.w);
#pragma unroll
            for (int i = 0; i < 4; i++)
#pragma unroll
                for (int j = 0; j < 8; j++)
                    acc[i][j] = fma2(a2[i], bd[j], acc[i][j]);
        }
        __syncthreads();
    }

    // ---- epilogue ----
#pragma unroll
    for (int i = 0; i < 4; i++) {
        int row0 = r0 + ty * 8 + 2 * i;
#pragma unroll
        for (int j = 0; j < 8; j++) {
            int col = tx * 8 + j;
            if (col < NOUT) {
                float lo, hi;
                unpack2(acc[i][j], lo, hi);
                float b = bias[col];
                float v0 = lo + b;
                float v1 = hi + b;
                if (RELU) {
                    v0 = fmaxf(v0, 0.f);
                    v1 = fmaxf(v1, 0.f);
                }
                if (row0 < N_NODES) out[(size_t)row0 * NOUT + col] = v0;
                if (row0 + 1 < N_NODES) out[(size_t)(row0 + 1) * NOUT + col] = v1;
            }
        }
    }
}

// ---------------- launch ----------------
extern "C" void kernel_launch(void* const* d_in, const int* in_sizes, int n_in,
                              void* d_out, int out_size) {
    const float* embed  = (const float*)d_in[0];
    const float* Wself0 = (const float*)d_in[1];
    const float* Wneigh0= (const float*)d_in[2];
    const float* b0     = (const float*)d_in[3];
    const float* Wself1 = (const float*)d_in[4];
    const float* Wneigh1= (const float*)d_in[5];
    const float* b1     = (const float*)d_in[6];
    const float* Wself2 = (const float*)d_in[7];
    const float* Wneigh2= (const float*)d_in[8];
    const float* b2     = (const float*)d_in[9];
    const int* input_nodes = (const int*)d_in[10];
    const int* src      = (const int*)d_in[11];
    const int* dst      = (const int*)d_in[12];
    float* out = (float*)d_out;

    float *h0, *h1, *agg, *deg, *inv;
    cudaGetSymbolAddress((void**)&h0, g_h0);
    cudaGetSymbolAddress((void**)&h1, g_h1);
    cudaGetSymbolAddress((void**)&agg, g_agg);
    cudaGetSymbolAddress((void**)&deg, g_deg);
    cudaGetSymbolAddress((void**)&inv, g_inv);

    const int T = 256;
    const int nf4 = N_NODES * 32;                 // float4 count of a feature buffer
    const int gemm_blocks = (N_NODES + 127) / 128;

    // degree (shared by all 3 layers) + embedding gather
    zero_f4<<<(N_NODES / 4 + T - 1) / T, T>>>((float4*)deg, N_NODES / 4);
    deg_kernel<<<(N_EDGES + T - 1) / T, T>>>(dst, deg);
    invdeg_kernel<<<(N_NODES + T - 1) / T, T>>>(deg, inv);
    gather_kernel<<<(N_NODES * 32 + T - 1) / T, T>>>(embed, input_nodes, h0);

    // layer 0: h0 -> h1 (relu)
    zero_f4<<<(nf4 + T - 1) / T, T>>>((float4*)agg, nf4);
    scatter_kernel<<<(N_EDGES * 32 + T - 1) / T, T>>>(h0, src, dst, agg);
    gemm_kernel<128, true><<<gemm_blocks, T>>>(h0, agg, inv, Wneigh0, Wself0, b0, h1);

    // layer 1: h1 -> h0 (relu)
    zero_f4<<<(nf4 + T - 1) / T, T>>>((float4*)agg, nf4);
    scatter_kernel<<<(N_EDGES * 32 + T - 1) / T, T>>>(h1, src, dst, agg);
    gemm_kernel<128, true><<<gemm_blocks, T>>>(h1, agg, inv, Wneigh1, Wself1, b1, h0);

    // layer 2: h0 -> out (no relu, 47 classes)
    zero_f4<<<(nf4 + T - 1) / T, T>>>((float4*)agg, nf4);
    scatter_kernel<<<(N_EDGES * 32 + T - 1) / T, T>>>(h0, src, dst, agg);
    gemm_kernel<NCLS, false><<<gemm_blocks, T>>>(h0, agg, inv, Wneigh2, Wself2, b2, out);
}

// round 3
// speedup vs baseline: 1.4705x; 1.4705x over previous
#include <cuda_runtime.h>
#include <cuda_bf16.h>

#define N_NODES 100000
#define N_EDGES 1600000
#define FEAT 128
#define NCLS 47
#define SCAN_BLK 1024
#define N_SCAN_BLKS ((N_NODES + SCAN_BLK - 1) / SCAN_BLK)   // 98

// ---------------- scratch (no allocation allowed) ----------------
__device__ __align__(16) float g_h0[N_NODES * FEAT];
__device__ __align__(16) float g_h1[N_NODES * FEAT];
__device__ __align__(16) float g_mean[N_NODES * FEAT];
__device__ __align__(16) int   g_cnt[N_NODES];
__device__ __align__(16) int   g_off[N_NODES + 1];
__device__ __align__(16) int   g_cur[N_NODES];
__device__ __align__(16) int   g_esrc[N_EDGES];
__device__ __align__(16) int   g_blksum[N_SCAN_BLKS];

// ---------------- packed f32x2 helpers ----------------
__device__ __forceinline__ unsigned long long pack2(float x, float y) {
    unsigned long long r;
    asm("mov.b64 %0, {%1, %2};" : "=l"(r) : "f"(x), "f"(y));
    return r;
}
__device__ __forceinline__ unsigned long long dup2(float x) {
    unsigned long long r;
    asm("mov.b64 %0, {%1, %1};" : "=l"(r) : "f"(x));
    return r;
}
__device__ __forceinline__ void unpack2(unsigned long long v, float& x, float& y) {
    asm("mov.b64 {%0, %1}, %2;" : "=f"(x), "=f"(y) : "l"(v));
}
__device__ __forceinline__ unsigned long long fma2(unsigned long long a,
                                                   unsigned long long b,
                                                   unsigned long long c) {
    unsigned long long d;
    asm("fma.rn.f32x2 %0, %1, %2, %3;" : "=l"(d) : "l"(a), "l"(b), "l"(c));
    return d;
}

// ---------------- CSR build ----------------
__global__ void zero_int(int* p, int n) {
    int i = blockIdx.x * blockDim.x + threadIdx.x;
    if (i < n) p[i] = 0;
}

__global__ void hist_kernel(const int* __restrict__ dst, int* __restrict__ cnt) {
    int e = blockIdx.x * blockDim.x + threadIdx.x;
    if (e < N_EDGES) atomicAdd(&cnt[dst[e]], 1);
}

// per-block exclusive scan (1024 elems), writes block total
__global__ void scan1_kernel(const int* __restrict__ cnt, int* __restrict__ excl,
                             int* __restrict__ blksum) {
    __shared__ int sh[SCAN_BLK];
    int tid = threadIdx.x;
    int i = blockIdx.x * SCAN_BLK + tid;
    int v = (i < N_NODES) ? cnt[i] : 0;
    sh[tid] = v;
    __syncthreads();
#pragma unroll
    for (int off = 1; off < SCAN_BLK; off <<= 1) {
        int t = (tid >= off) ? sh[tid - off] : 0;
        __syncthreads();
        sh[tid] += t;
        __syncthreads();
    }
    if (i <= N_NODES) excl[i] = sh[tid] - v;  // exclusive
    if (tid == SCAN_BLK - 1) blksum[blockIdx.x] = sh[tid];
}

// serial scan of the (98) block sums — tiny
__global__ void scan2_kernel(int* __restrict__ blksum) {
    __shared__ int sh[N_SCAN_BLKS];
    int tid = threadIdx.x;
    if (tid < N_SCAN_BLKS) sh[tid] = blksum[tid];
    __syncthreads();
    if (tid == 0) {
        int run = 0;
        for (int b = 0; b < N_SCAN_BLKS; b++) {
            int t = sh[b];
            sh[b] = run;
            run += t;
        }
    }
    __syncthreads();
    if (tid < N_SCAN_BLKS) blksum[tid] = sh[tid];
}

__global__ void scan3_kernel(int* __restrict__ excl, const int* __restrict__ blksum,
                             int* __restrict__ cur) {
    int i = blockIdx.x * blockDim.x + threadIdx.x;
    if (i < N_NODES) {
        int v = excl[i] + blksum[i / SCAN_BLK];
        excl[i] = v;
        cur[i] = v;
    }
    if (i == 0) excl[N_NODES] = N_EDGES;
}

__global__ void fill_kernel(const int* __restrict__ src, const int* __restrict__ dst,
                            int* __restrict__ cur, int* __restrict__ esrc) {
    int e = blockIdx.x * blockDim.x + threadIdx.x;
    if (e < N_EDGES) {
        int pos = atomicAdd(&cur[dst[e]], 1);
        esrc[pos] = src[e];
    }
}

// ---------------- gather embedding ----------------
__global__ void gather_kernel(const float* __restrict__ embed,
                              const int* __restrict__ nodes,
                              float* __restrict__ h0) {
    int t = blockIdx.x * blockDim.x + threadIdx.x;
    int v = t >> 5, l = t & 31;
    if (v < N_NODES) {
        int s = nodes[v];
        reinterpret_cast<float4*>(h0)[v * 32 + l] =
            reinterpret_cast<const float4*>(embed)[s * 32 + l];
    }
}

// ---------------- CSR mean aggregation: warp per node, no atomics ----------------
__global__ void agg_kernel(const float* __restrict__ h,
                           const int* __restrict__ esrc,
                           const int* __restrict__ off,
                           float* __restrict__ mean) {
    int t = blockIdx.x * blockDim.x + threadIdx.x;
    int v = t >> 5, l = t & 31;
    if (v >= N_NODES) return;
    int beg = off[v];
    int end = off[v + 1];
    const float4* h4 = reinterpret_cast<const float4*>(h);
    float4 acc = make_float4(0.f, 0.f, 0.f, 0.f);
    int j = beg;
    // unroll by 4 for MLP
    for (; j + 4 <= end; j += 4) {
        int s0 = esrc[j], s1 = esrc[j + 1], s2 = esrc[j + 2], s3 = esrc[j + 3];
        float4 v0 = h4[s0 * 32 + l];
        float4 v1 = h4[s1 * 32 + l];
        float4 v2 = h4[s2 * 32 + l];
        float4 v3 = h4[s3 * 32 + l];
        acc.x += (v0.x + v1.x) + (v2.x + v3.x);
        acc.y += (v0.y + v1.y) + (v2.y + v3.y);
        acc.z += (v0.z + v1.z) + (v2.z + v3.z);
        acc.w += (v0.w + v1.w) + (v2.w + v3.w);
    }
    for (; j < end; j++) {
        float4 vv = h4[esrc[j] * 32 + l];
        acc.x += vv.x; acc.y += vv.y; acc.z += vv.z; acc.w += vv.w;
    }
    float invd = 1.0f / fmaxf((float)(end - beg), 1.0f);
    acc.x *= invd; acc.y *= invd; acc.z *= invd; acc.w *= invd;
    reinterpret_cast<float4*>(mean)[v * 32 + l] = acc;
}

// ---------------- fused dual GEMM ----------------
// out[v,:] = mean[v] @ Wn + h[v] @ Ws + b    (optionally ReLU)
// K = 256, BM=128, BN=128, BK=16, 256 threads, 8x8 micro-tile, FFMA2 pairs.
template <int NOUT, bool RELU>
__global__ void __launch_bounds__(256) gemm_kernel(
    const float* __restrict__ h, const float* __restrict__ mean,
    const float* __restrict__ Wn, const float* __restrict__ Ws,
    const float* __restrict__ bias, float* __restrict__ out) {
    __shared__ float As[16][132];   // [k][m], padded
    __shared__ float Bs[16][128];   // [k][n]

    const int tid = threadIdx.x;
    const int r0 = blockIdx.x * 128;
    const int tx = tid & 15;   // col group (8 cols)
    const int ty = tid >> 4;   // row group (8 rows)

    unsigned long long acc[4][8];
#pragma unroll
    for (int i = 0; i < 4; i++)
#pragma unroll
        for (int j = 0; j < 8; j++) acc[i][j] = 0ull;

    for (int k0 = 0; k0 < 256; k0 += 16) {
        // ---- load A tile (128 rows x 16 k) from mean (k<128) / h (k>=128) ----
#pragma unroll
        for (int p = 0; p < 2; p++) {
            int idx4 = tid + p * 256;
            int m = idx4 >> 2;
            int kl = (idx4 & 3) * 4;
            int row = r0 + m;
            float4 v = make_float4(0.f, 0.f, 0.f, 0.f);
            if (row < N_NODES) {
                int kg = k0 + kl;
                if (kg < 128)
                    v = reinterpret_cast<const float4*>(mean)[row * 32 + (kg >> 2)];
                else
                    v = reinterpret_cast<const float4*>(h)[row * 32 + ((kg - 128) >> 2)];
            }
            As[kl + 0][m] = v.x;
            As[kl + 1][m] = v.y;
            As[kl + 2][m] = v.z;
            As[kl + 3][m] = v.w;
        }
        // ---- load B tile (16 k x 128 n) from Wn/Ws ----
#pragma unroll
        for (int p = 0; p < 8; p++) {
            int idx = tid + p * 256;
            int k = idx >> 7;
            int n = idx & 127;
            int kg = k0 + k;
            float w = 0.f;
            if (n < NOUT)
                w = (kg < 128) ? Wn[kg * NOUT + n] : Ws[(kg - 128) * NOUT + n];
            Bs[k][n] = w;
        }
        __syncthreads();

#pragma unroll
        for (int kk = 0; kk < 16; kk++) {
            const float2* a2p = reinterpret_cast<const float2*>(&As[kk][ty * 8]);
            unsigned long long a2[4];
#pragma unroll
            for (int i = 0; i < 4; i++) {
                float2 t = a2p[i];
                a2[i] = pack2(t.x, t.y);
            }
            const float4* b4p = reinterpret_cast<const float4*>(&Bs[kk][tx * 8]);
            float4 bA = b4p[0];
            float4 bB = b4p[1];
            unsigned long long bd[8];
            bd[0] = dup2(bA.x); bd[1] = dup2(bA.y); bd[2] = dup2(bA.z); bd[3] = dup2(bA.w);
            bd[4] = dup2(bB.x); bd[5] = dup2(bB.y); bd[6] = dup2(bB.z); bd[7] = dup2(bB.w);
#pragma unroll
            for (int i = 0; i < 4; i++)
#pragma unroll
                for (int j = 0; j < 8; j++)
                    acc[i][j] = fma2(a2[i], bd[j], acc[i][j]);
        }
        __syncthreads();
    }

    // ---- epilogue ----
#pragma unroll
    for (int i = 0; i < 4; i++) {
        int row0 = r0 + ty * 8 + 2 * i;
#pragma unroll
        for (int j = 0; j < 8; j++) {
            int col = tx * 8 + j;
            if (col < NOUT) {
                float lo, hi;
                unpack2(acc[i][j], lo, hi);
                float b = bias[col];
                float v0 = lo + b;
                float v1 = hi + b;
                if (RELU) {
                    v0 = fmaxf(v0, 0.f);
                    v1 = fmaxf(v1, 0.f);
                }
                if (row0 < N_NODES) out[(size_t)row0 * NOUT + col] = v0;
                if (row0 + 1 < N_NODES) out[(size_t)(row0 + 1) * NOUT + col] = v1;
            }
        }
    }
}

// ---------------- launch ----------------
extern "C" void kernel_launch(void* const* d_in, const int* in_sizes, int n_in,
                              void* d_out, int out_size) {
    const float* embed  = (const float*)d_in[0];
    const float* Wself0 = (const float*)d_in[1];
    const float* Wneigh0= (const float*)d_in[2];
    const float* b0     = (const float*)d_in[3];
    const float* Wself1 = (const float*)d_in[4];
    const float* Wneigh1= (const float*)d_in[5];
    const float* b1     = (const float*)d_in[6];
    const float* Wself2 = (const float*)d_in[7];
    const float* Wneigh2= (const float*)d_in[8];
    const float* b2     = (const float*)d_in[9];
    const int* input_nodes = (const int*)d_in[10];
    const int* src      = (const int*)d_in[11];
    const int* dst      = (const int*)d_in[12];
    float* out = (float*)d_out;

    float *h0, *h1, *mean;
    int *cnt, *off, *cur, *esrc, *blksum;
    cudaGetSymbolAddress((void**)&h0, g_h0);
    cudaGetSymbolAddress((void**)&h1, g_h1);
    cudaGetSymbolAddress((void**)&mean, g_mean);
    cudaGetSymbolAddress((void**)&cnt, g_cnt);
    cudaGetSymbolAddress((void**)&off, g_off);
    cudaGetSymbolAddress((void**)&cur, g_cur);
    cudaGetSymbolAddress((void**)&esrc, g_esrc);
    cudaGetSymbolAddress((void**)&blksum, g_blksum);

    const int T = 256;
    const int gemm_blocks = (N_NODES + 127) / 128;
    const int warp_blocks = (N_NODES * 32 + T - 1) / T;

    // ---- CSR build (once; reused by all 3 layers) ----
    zero_int<<<(N_NODES + T - 1) / T, T>>>(cnt, N_NODES);
    hist_kernel<<<(N_EDGES + T - 1) / T, T>>>(dst, cnt);
    scan1_kernel<<<N_SCAN_BLKS, SCAN_BLK>>>(cnt, off, blksum);
    scan2_kernel<<<1, 128>>>(blksum);
    scan3_kernel<<<(N_NODES + T - 1) / T, T>>>(off, blksum, cur);
    fill_kernel<<<(N_EDGES + T - 1) / T, T>>>(src, dst, cur, esrc);

    // ---- embedding gather ----
    gather_kernel<<<warp_blocks, T>>>(embed, input_nodes, h0);

    // layer 0: h0 -> h1 (relu)
    agg_kernel<<<warp_blocks, T>>>(h0, esrc, off, mean);
    gemm_kernel<128, true><<<gemm_blocks, T>>>(h0, mean, Wneigh0, Wself0, b0, h1);

    // layer 1: h1 -> h0 (relu)
    agg_kernel<<<warp_blocks, T>>>(h1, esrc, off, mean);
    gemm_kernel<128, true><<<gemm_blocks, T>>>(h1, mean, Wneigh1, Wself1, b1, h0);

    // layer 2: h0 -> out (no relu, 47 classes)
    agg_kernel<<<warp_blocks, T>>>(h0, esrc, off, mean);
    gemm_kernel<NCLS, false><<<gemm_blocks, T>>>(h0, mean, Wneigh2, Wself2, b2, out);
}

// round 5
// speedup vs baseline: 2.9817x; 2.0277x over previous
#include <cuda_runtime.h>
#include <cuda_bf16.h>
#include <cstdint>

#define N_NODES 100000
#define N_EDGES 1600000
#define FEAT 128
#define NCLS 47
#define SCAN_BLK 1024
#define N_SCAN_BLKS ((N_NODES + SCAN_BLK - 1) / SCAN_BLK)   // 98

// ---------------- scratch (no allocation allowed) ----------------
__device__ __align__(16) float g_h0[N_NODES * FEAT];
__device__ __align__(16) float g_h1[N_NODES * FEAT];
__device__ __align__(16) float g_mean[N_NODES * FEAT];
__device__ __align__(16) int   g_cnt[N_NODES];
__device__ __align__(16) int   g_off[N_NODES + 1];
__device__ __align__(16) int   g_cur[N_NODES];
__device__ __align__(16) int   g_esrc[N_EDGES];
__device__ __align__(16) int   g_blksum[N_SCAN_BLKS];

// ---------------- PTX helpers ----------------
__device__ __forceinline__ uint32_t smem_u32(const void* p) {
    uint32_t a;
    asm("{ .reg .u64 t; cvta.to.shared.u64 t, %1; cvt.u32.u64 %0, t; }"
        : "=r"(a) : "l"(p));
    return a;
}
__device__ __forceinline__ void ldsm4(uint32_t* r, uint32_t a) {
    asm volatile("ldmatrix.sync.aligned.m8n8.x4.shared.b16 {%0,%1,%2,%3}, [%4];"
                 : "=r"(r[0]), "=r"(r[1]), "=r"(r[2]), "=r"(r[3]) : "r"(a));
}
__device__ __forceinline__ void ldsm4t(uint32_t* r, uint32_t a) {
    asm volatile("ldmatrix.sync.aligned.m8n8.x4.trans.shared.b16 {%0,%1,%2,%3}, [%4];"
                 : "=r"(r[0]), "=r"(r[1]), "=r"(r[2]), "=r"(r[3]) : "r"(a));
}
__device__ __forceinline__ void mma_bf16(float* d, const uint32_t* a, const uint32_t* b) {
    asm volatile(
        "mma.sync.aligned.m16n8k16.row.col.f32.bf16.bf16.f32 "
        "{%0,%1,%2,%3}, {%4,%5,%6,%7}, {%8,%9}, {%0,%1,%2,%3};"
        : "+f"(d[0]), "+f"(d[1]), "+f"(d[2]), "+f"(d[3])
        : "r"(a[0]), "r"(a[1]), "r"(a[2]), "r"(a[3]), "r"(b[0]), "r"(b[1]));
}
__device__ __forceinline__ uint32_t pack_bf2(float x, float y) {
    __nv_bfloat162 t = __halves2bfloat162(__float2bfloat16_rn(x), __float2bfloat16_rn(y));
    return *reinterpret_cast<uint32_t*>(&t);
}
__device__ __forceinline__ void split_bf(float x, __nv_bfloat16& hi, __nv_bfloat16& lo) {
    hi = __float2bfloat16_rn(x);
    lo = __float2bfloat16_rn(x - __bfloat162float(hi));
}

// ---------------- CSR build ----------------
__global__ void zero_int(int* p, int n) {
    int i = blockIdx.x * blockDim.x + threadIdx.x;
    if (i < n) p[i] = 0;
}
__global__ void hist_kernel(const int* __restrict__ dst, int* __restrict__ cnt) {
    int e = blockIdx.x * blockDim.x + threadIdx.x;
    if (e < N_EDGES) atomicAdd(&cnt[dst[e]], 1);
}
__global__ void scan1_kernel(const int* __restrict__ cnt, int* __restrict__ excl,
                             int* __restrict__ blksum) {
    __shared__ int sh[SCAN_BLK];
    int tid = threadIdx.x;
    int i = blockIdx.x * SCAN_BLK + tid;
    int v = (i < N_NODES) ? cnt[i] : 0;
    sh[tid] = v;
    __syncthreads();
#pragma unroll
    for (int off = 1; off < SCAN_BLK; off <<= 1) {
        int t = (tid >= off) ? sh[tid - off] : 0;
        __syncthreads();
        sh[tid] += t;
        __syncthreads();
    }
    if (i <= N_NODES) excl[i] = sh[tid] - v;
    if (tid == SCAN_BLK - 1) blksum[blockIdx.x] = sh[tid];
}
__global__ void scan2_kernel(int* __restrict__ blksum) {
    __shared__ int sh[N_SCAN_BLKS];
    int tid = threadIdx.x;
    if (tid < N_SCAN_BLKS) sh[tid] = blksum[tid];
    __syncthreads();
    if (tid == 0) {
        int run = 0;
        for (int b = 0; b < N_SCAN_BLKS; b++) {
            int t = sh[b];
            sh[b] = run;
            run += t;
        }
    }
    __syncthreads();
    if (tid < N_SCAN_BLKS) blksum[tid] = sh[tid];
}
__global__ void scan3_kernel(int* __restrict__ excl, const int* __restrict__ blksum,
                             int* __restrict__ cur) {
    int i = blockIdx.x * blockDim.x + threadIdx.x;
    if (i < N_NODES) {
        int v = excl[i] + blksum[i / SCAN_BLK];
        excl[i] = v;
        cur[i] = v;
    }
    if (i == 0) excl[N_NODES] = N_EDGES;
}
__global__ void fill_kernel(const int* __restrict__ src, const int* __restrict__ dst,
                            int* __restrict__ cur, int* __restrict__ esrc) {
    int e = blockIdx.x * blockDim.x + threadIdx.x;
    if (e < N_EDGES) {
        int pos = atomicAdd(&cur[dst[e]], 1);
        esrc[pos] = src[e];
    }
}

// ---------------- gather embedding ----------------
__global__ void gather_kernel(const float* __restrict__ embed,
                              const int* __restrict__ nodes,
                              float* __restrict__ h0) {
    int t = blockIdx.x * blockDim.x + threadIdx.x;
    int v = t >> 5, l = t & 31;
    if (v < N_NODES) {
        int s = nodes[v];
        reinterpret_cast<float4*>(h0)[v * 32 + l] =
            reinterpret_cast<const float4*>(embed)[s * 32 + l];
    }
}

// ---------------- CSR mean aggregation: warp per node, no atomics ----------------
__global__ void agg_kernel(const float* __restrict__ h,
                           const int* __restrict__ esrc,
                           const int* __restrict__ off,
                           float* __restrict__ mean) {
    int t = blockIdx.x * blockDim.x + threadIdx.x;
    int v = t >> 5, l = t & 31;
    if (v >= N_NODES) return;
    int beg = off[v];
    int end = off[v + 1];
    const float4* h4 = reinterpret_cast<const float4*>(h);
    float4 acc = make_float4(0.f, 0.f, 0.f, 0.f);
    int j = beg;
    for (; j + 4 <= end; j += 4) {
        int s0 = esrc[j], s1 = esrc[j + 1], s2 = esrc[j + 2], s3 = esrc[j + 3];
        float4 v0 = h4[s0 * 32 + l];
        float4 v1 = h4[s1 * 32 + l];
        float4 v2 = h4[s2 * 32 + l];
        float4 v3 = h4[s3 * 32 + l];
        acc.x += (v0.x + v1.x) + (v2.x + v3.x);
        acc.y += (v0.y + v1.y) + (v2.y + v3.y);
        acc.z += (v0.z + v1.z) + (v2.z + v3.z);
        acc.w += (v0.w + v1.w) + (v2.w + v3.w);
    }
    for (; j < end; j++) {
        float4 vv = h4[esrc[j] * 32 + l];
        acc.x += vv.x; acc.y += vv.y; acc.z += vv.z; acc.w += vv.w;
    }
    float invd = 1.0f / fmaxf((float)(end - beg), 1.0f);
    acc.x *= invd; acc.y *= invd; acc.z *= invd; acc.w *= invd;
    reinterpret_cast<float4*>(mean)[v * 32 + l] = acc;
}

// ---------------- mma.sync dual GEMM (bf16 hi/lo split -> fp32 accuracy) ----------------
// out[v,:] = mean[v] @ Wn + h[v] @ Ws + b  (optional ReLU)
// BM=128, BN=128 or 64, K=256 in 4 chunks of 64. 8 warps (4 along M x 2 along N).
// Each warp: 2 m-tiles (16) x NT n-tiles (8). 3 MMAs per tile (hh, hl, lh).
//
// Dynamic SMEM:
//   [0]      bias (512B)
//   [1024]   A_hi 128x64 bf16 (128B rows, XOR-swizzled)     16KB
//   [17408]  A_lo                                           16KB
//   [33792]  B_hi 64 x BN bf16 (BN*2-byte rows, swizzled)   BN*128 bytes
//   [33792+BN*128] B_lo
template <int BN, int NOUT, bool RELU>
__global__ void __launch_bounds__(256) gemm_mma(
    const float* __restrict__ h, const float* __restrict__ mean,
    const float* __restrict__ Wn, const float* __restrict__ Ws,
    const float* __restrict__ bias, float* __restrict__ out) {
    extern __shared__ char smem[];
    const uint32_t sb = smem_u32(smem);
    const int tid = threadIdx.x;
    const int wid = tid >> 5;
    const int lane = tid & 31;
    const int wm = wid >> 1;        // 0..3 (32 rows each)
    const int wn = wid & 1;         // 0..1 (BN/2 cols each)
    const int r0 = blockIdx.x * 128;

    constexpr int HN = BN / 2;
    constexpr int NT = HN / 8;
    constexpr uint32_t A_HI = 1024;
    constexpr uint32_t A_LO = 1024 + 16384;
    constexpr uint32_t B_HI = 1024 + 32768;
    constexpr uint32_t B_LO = B_HI + (uint32_t)BN * 128;

    if (tid < NOUT) *reinterpret_cast<float*>(smem + tid * 4) = bias[tid];

    const float4* mean4 = reinterpret_cast<const float4*>(mean);
    const float4* h4 = reinterpret_cast<const float4*>(h);

    float acc[2][NT][4];
#pragma unroll
    for (int i = 0; i < 2; i++)
#pragma unroll
        for (int j = 0; j < NT; j++)
#pragma unroll
            for (int q = 0; q < 4; q++) acc[i][j][q] = 0.f;

    for (int c = 0; c < 4; c++) {
        __syncthreads();   // smem free (also covers bias on first iter)

        // ---- A chunk: 128 rows x 64 floats -> bf16 hi/lo (8 float4 per thread) ----
#pragma unroll
        for (int it = 0; it < 8; it++) {
            int idx = tid + it * 256;
            int m = idx >> 4;
            int q = idx & 15;
            int row = r0 + m;
            float4 v = make_float4(0.f, 0.f, 0.f, 0.f);
            if (row < N_NODES)
                v = (c < 2) ? mean4[row * 32 + c * 16 + q]
                            : h4[row * 32 + (c - 2) * 16 + q];
            __nv_bfloat16 h0b, h1b, h2b, h3b, l0b, l1b, l2b, l3b;
            split_bf(v.x, h0b, l0b);
            split_bf(v.y, h1b, l1b);
            split_bf(v.z, h2b, l2b);
            split_bf(v.w, h3b, l3b);
            uint32_t off = (uint32_t)(m * 128 + q * 8);
            off ^= (uint32_t)(m & 7) << 4;
            __nv_bfloat162 hh0 = __halves2bfloat162(h0b, h1b);
            __nv_bfloat162 hh1 = __halves2bfloat162(h2b, h3b);
            __nv_bfloat162 ll0 = __halves2bfloat162(l0b, l1b);
            __nv_bfloat162 ll1 = __halves2bfloat162(l2b, l3b);
            *reinterpret_cast<uint2*>(smem + A_HI + off) =
                make_uint2(*reinterpret_cast<uint32_t*>(&hh0), *reinterpret_cast<uint32_t*>(&hh1));
            *reinterpret_cast<uint2*>(smem + A_LO + off) =
                make_uint2(*reinterpret_cast<uint32_t*>(&ll0), *reinterpret_cast<uint32_t*>(&ll1));
        }

        // ---- B chunk: 64 k-rows x BN cols of W (zero-padded to BN) ----
        {
            const float* W = (c < 2) ? Wn : Ws;
            int kb = (c & 1) * 64;
            if (BN == 128 && NOUT == 128) {
                const float4* W4 = reinterpret_cast<const float4*>(W);
#pragma unroll
                for (int it = 0; it < 8; it++) {
                    int idx = tid + it * 256;
                    int k = idx >> 5;
                    int nq = idx & 31;
                    float4 v = W4[(kb + k) * 32 + nq];
                    __nv_bfloat16 h0b, h1b, h2b, h3b, l0b, l1b, l2b, l3b;
                    split_bf(v.x, h0b, l0b);
                    split_bf(v.y, h1b, l1b);
                    split_bf(v.z, h2b, l2b);
                    split_bf(v.w, h3b, l3b);
                    uint32_t off = (uint32_t)(k * 256 + nq * 8);
                    off ^= (uint32_t)(k & 7) << 4;
                    __nv_bfloat162 hh0 = __halves2bfloat162(h0b, h1b);
                    __nv_bfloat162 hh1 = __halves2bfloat162(h2b, h3b);
                    __nv_bfloat162 ll0 = __halves2bfloat162(l0b, l1b);
                    __nv_bfloat162 ll1 = __halves2bfloat162(l2b, l3b);
                    *reinterpret_cast<uint2*>(smem + B_HI + off) =
                        make_uint2(*reinterpret_cast<uint32_t*>(&hh0), *reinterpret_cast<uint32_t*>(&hh1));
                    *reinterpret_cast<uint2*>(smem + B_LO + off) =
                        make_uint2(*reinterpret_cast<uint32_t*>(&ll0), *reinterpret_cast<uint32_t*>(&ll1));
                }
            } else {
#pragma unroll
                for (int it = 0; it < BN * 64 / 256; it++) {
                    int idx = tid + it * 256;
                    int k = idx / BN;
                    int n = idx % BN;
                    float w = (n < NOUT) ? W[(kb + k) * NOUT + n] : 0.f;
                    __nv_bfloat16 hi, lo;
                    split_bf(w, hi, lo);
                    uint32_t off = (uint32_t)(k * BN * 2 + n * 2);
                    off ^= (uint32_t)(k & 7) << 4;
                    *reinterpret_cast<__nv_bfloat16*>(smem + B_HI + off) = hi;
                    *reinterpret_cast<__nv_bfloat16*>(smem + B_LO + off) = lo;
                }
            }
        }
        __syncthreads();

        // ---- compute: 4 k-steps of 16 ----
#pragma unroll
        for (int kt = 0; kt < 4; kt++) {
            uint32_t ah[2][4], al[2][4];
            int arow_base = wm * 32 + (lane & 15);
            int akb = kt * 32 + ((lane >> 4) << 4);
#pragma unroll
            for (int mt = 0; mt < 2; mt++) {
                int row = arow_base + mt * 16;
                uint32_t off = (uint32_t)(row * 128 + akb);
                off ^= (uint32_t)(row & 7) << 4;
                ldsm4(ah[mt], sb + A_HI + off);
                ldsm4(al[mt], sb + A_LO + off);
            }
            int bk = kt * 16 + (lane & 15);
#pragma unroll
            for (int np = 0; np < NT / 2; np++) {
                int n0 = wn * HN + np * 16 + ((lane >> 4) << 3);
                uint32_t off = (uint32_t)(bk * BN * 2 + n0 * 2);
                off ^= (uint32_t)(bk & 7) << 4;
                uint32_t bh[4], bl[4];
                ldsm4t(bh, sb + B_HI + off);
                ldsm4t(bl, sb + B_LO + off);
#pragma unroll
                for (int hh = 0; hh < 2; hh++) {
                    int nt = np * 2 + hh;
#pragma unroll
                    for (int mt = 0; mt < 2; mt++) {
                        mma_bf16(acc[mt][nt], ah[mt], bh + 2 * hh);
                        mma_bf16(acc[mt][nt], ah[mt], bl + 2 * hh);
                        mma_bf16(acc[mt][nt], al[mt], bh + 2 * hh);
                    }
                }
            }
        }
    }

    // ---- epilogue ----
    const float* biasS = reinterpret_cast<const float*>(smem);
#pragma unroll
    for (int mt = 0; mt < 2; mt++) {
        int row = r0 + wm * 32 + mt * 16 + (lane >> 2);
#pragma unroll
        for (int nt = 0; nt < NT; nt++) {
            int col = wn * HN + nt * 8 + (lane & 3) * 2;
#pragma unroll
            for (int p = 0; p < 2; p++) {
                int r = row + p * 8;
                if (r < N_NODES) {
                    float v0 = acc[mt][nt][2 * p + 0];
                    float v1 = acc[mt][nt][2 * p + 1];
                    if (col < NOUT) {
                        float v = v0 + biasS[col];
                        if (RELU) v = fmaxf(v, 0.f);
                        out[(size_t)r * NOUT + col] = v;
                    }
                    if (col + 1 < NOUT) {
                        float v = v1 + biasS[col + 1];
                        if (RELU) v = fmaxf(v, 0.f);
                        out[(size_t)r * NOUT + col + 1] = v;
                    }
                }
            }
        }
    }
}

// ---------------- launch ----------------
extern "C" void kernel_launch(void* const* d_in, const int* in_sizes, int n_in,
                              void* d_out, int out_size) {
    const float* embed  = (const float*)d_in[0];
    const float* Wself0 = (const float*)d_in[1];
    const float* Wneigh0= (const float*)d_in[2];
    const float* b0     = (const float*)d_in[3];
    const float* Wself1 = (const float*)d_in[4];
    const float* Wneigh1= (const float*)d_in[5];
    const float* b1     = (const float*)d_in[6];
    const float* Wself2 = (const float*)d_in[7];
    const float* Wneigh2= (const float*)d_in[8];
    const float* b2     = (const float*)d_in[9];
    const int* input_nodes = (const int*)d_in[10];
    const int* src      = (const int*)d_in[11];
    const int* dst      = (const int*)d_in[12];
    float* out = (float*)d_out;

    float *h0, *h1, *mean;
    int *cnt, *off, *cur, *esrc, *blksum;
    cudaGetSymbolAddress((void**)&h0, g_h0);
    cudaGetSymbolAddress((void**)&h1, g_h1);
    cudaGetSymbolAddress((void**)&mean, g_mean);
    cudaGetSymbolAddress((void**)&cnt, g_cnt);
    cudaGetSymbolAddress((void**)&off, g_off);
    cudaGetSymbolAddress((void**)&cur, g_cur);
    cudaGetSymbolAddress((void**)&esrc, g_esrc);
    cudaGetSymbolAddress((void**)&blksum, g_blksum);

    const int T = 256;
    const int gemm_blocks = (N_NODES + 127) / 128;           // 782
    const int warp_blocks = (N_NODES * 32 + T - 1) / T;

    const int SMEM_128 = 1024 + 32768 + 2 * 128 * 128;       // 66560
    const int SMEM_64  = 1024 + 32768 + 2 * 64 * 128;        // 50176
    cudaFuncSetAttribute(gemm_mma<128, 128, true>,
                         cudaFuncAttributeMaxDynamicSharedMemorySize, SMEM_128);
    cudaFuncSetAttribute(gemm_mma<64, NCLS, false>,
                         cudaFuncAttributeMaxDynamicSharedMemorySize, SMEM_64);

    // ---- CSR build (once; reused by all 3 layers) ----
    zero_int<<<(N_NODES + T - 1) / T, T>>>(cnt, N_NODES);
    hist_kernel<<<(N_EDGES + T - 1) / T, T>>>(dst, cnt);
    scan1_kernel<<<N_SCAN_BLKS, SCAN_BLK>>>(cnt, off, blksum);
    scan2_kernel<<<1, 128>>>(blksum);
    scan3_kernel<<<(N_NODES + T - 1) / T, T>>>(off, blksum, cur);
    fill_kernel<<<(N_EDGES + T - 1) / T, T>>>(src, dst, cur, esrc);

    // ---- embedding gather ----
    gather_kernel<<<warp_blocks, T>>>(embed, input_nodes, h0);

    // layer 0: h0 -> h1 (relu)
    agg_kernel<<<warp_blocks, T>>>(h0, esrc, off, mean);
    gemm_mma<128, 128, true><<<gemm_blocks, T, SMEM_128>>>(h0, mean, Wneigh0, Wself0, b0, h1);

    // layer 1: h1 -> h0 (relu)
    agg_kernel<<<warp_blocks, T>>>(h1, esrc, off, mean);
    gemm_mma<128, 128, true><<<gemm_blocks, T, SMEM_128>>>(h1, mean, Wneigh1, Wself1, b1, h0);

    // layer 2: h0 -> out (no relu, 47 classes)
    agg_kernel<<<warp_blocks, T>>>(h0, esrc, off, mean);
    gemm_mma<64, NCLS, false><<<gemm_blocks, T, SMEM_64>>>(h0, mean, Wneigh2, Wself2, b2, out);
}

// round 6
// speedup vs baseline: 3.0645x; 1.0278x over previous
#include <cuda_runtime.h>
#include <cuda_bf16.h>
#include <cstdint>

#define N_NODES 100000
#define N_EDGES 1600000
#define FEAT 128
#define NCLS 47
#define SCAN_BLK 1024
#define N_SCAN_BLKS ((N_NODES + SCAN_BLK - 1) / SCAN_BLK)   // 98

// ---------------- scratch (no allocation allowed) ----------------
__device__ __align__(16) float g_h0[N_NODES * FEAT];
__device__ __align__(16) float g_h1[N_NODES * FEAT];
__device__ __align__(16) float g_mean[N_NODES * FEAT];
__device__ __align__(16) __nv_bfloat16 g_hb0[N_NODES * FEAT];
__device__ __align__(16) __nv_bfloat16 g_hb1[N_NODES * FEAT];
__device__ __align__(16) int   g_cnt[N_NODES];
__device__ __align__(16) int   g_off[N_NODES + 1];
__device__ __align__(16) int   g_cur[N_NODES];
__device__ __align__(16) int   g_esrc[N_EDGES];
__device__ __align__(16) int   g_blksum[N_SCAN_BLKS];

// ---------------- PTX helpers ----------------
__device__ __forceinline__ uint32_t smem_u32(const void* p) {
    uint32_t a;
    asm("{ .reg .u64 t; cvta.to.shared.u64 t, %1; cvt.u32.u64 %0, t; }"
        : "=r"(a) : "l"(p));
    return a;
}
__device__ __forceinline__ void ldsm4(uint32_t* r, uint32_t a) {
    asm volatile("ldmatrix.sync.aligned.m8n8.x4.shared.b16 {%0,%1,%2,%3}, [%4];"
                 : "=r"(r[0]), "=r"(r[1]), "=r"(r[2]), "=r"(r[3]) : "r"(a));
}
__device__ __forceinline__ void ldsm4t(uint32_t* r, uint32_t a) {
    asm volatile("ldmatrix.sync.aligned.m8n8.x4.trans.shared.b16 {%0,%1,%2,%3}, [%4];"
                 : "=r"(r[0]), "=r"(r[1]), "=r"(r[2]), "=r"(r[3]) : "r"(a));
}
__device__ __forceinline__ void mma_bf16(float* d, const uint32_t* a, const uint32_t* b) {
    asm volatile(
        "mma.sync.aligned.m16n8k16.row.col.f32.bf16.bf16.f32 "
        "{%0,%1,%2,%3}, {%4,%5,%6,%7}, {%8,%9}, {%0,%1,%2,%3};"
        : "+f"(d[0]), "+f"(d[1]), "+f"(d[2]), "+f"(d[3])
        : "r"(a[0]), "r"(a[1]), "r"(a[2]), "r"(a[3]), "r"(b[0]), "r"(b[1]));
}
__device__ __forceinline__ void split_bf(float x, __nv_bfloat16& hi, __nv_bfloat16& lo) {
    hi = __float2bfloat16_rn(x);
    lo = __float2bfloat16_rn(x - __bfloat162float(hi));
}
__device__ __forceinline__ uint32_t pack_bf16x2(float lo_val, float hi_val) {
    __nv_bfloat162 t = __halves2bfloat162(__float2bfloat16_rn(lo_val),
                                          __float2bfloat16_rn(hi_val));
    return *reinterpret_cast<uint32_t*>(&t);
}

// ---------------- CSR build ----------------
__global__ void zero_int(int* p, int n) {
    int i = blockIdx.x * blockDim.x + threadIdx.x;
    if (i < n) p[i] = 0;
}
__global__ void hist_kernel(const int* __restrict__ dst, int* __restrict__ cnt) {
    int e = blockIdx.x * blockDim.x + threadIdx.x;
    if (e < N_EDGES) atomicAdd(&cnt[dst[e]], 1);
}
__global__ void scan1_kernel(const int* __restrict__ cnt, int* __restrict__ excl,
                             int* __restrict__ blksum) {
    __shared__ int sh[SCAN_BLK];
    int tid = threadIdx.x;
    int i = blockIdx.x * SCAN_BLK + tid;
    int v = (i < N_NODES) ? cnt[i] : 0;
    sh[tid] = v;
    __syncthreads();
#pragma unroll
    for (int off = 1; off < SCAN_BLK; off <<= 1) {
        int t = (tid >= off) ? sh[tid - off] : 0;
        __syncthreads();
        sh[tid] += t;
        __syncthreads();
    }
    if (i <= N_NODES) excl[i] = sh[tid] - v;
    if (tid == SCAN_BLK - 1) blksum[blockIdx.x] = sh[tid];
}
__global__ void scan2_kernel(int* __restrict__ blksum) {
    __shared__ int sh[N_SCAN_BLKS];
    int tid = threadIdx.x;
    if (tid < N_SCAN_BLKS) sh[tid] = blksum[tid];
    __syncthreads();
    if (tid == 0) {
        int run = 0;
        for (int b = 0; b < N_SCAN_BLKS; b++) {
            int t = sh[b];
            sh[b] = run;
            run += t;
        }
    }
    __syncthreads();
    if (tid < N_SCAN_BLKS) blksum[tid] = sh[tid];
}
__global__ void scan3_kernel(int* __restrict__ excl, const int* __restrict__ blksum,
                             int* __restrict__ cur) {
    int i = blockIdx.x * blockDim.x + threadIdx.x;
    if (i < N_NODES) {
        int v = excl[i] + blksum[i / SCAN_BLK];
        excl[i] = v;
        cur[i] = v;
    }
    if (i == 0) excl[N_NODES] = N_EDGES;
}
__global__ void fill_kernel(const int* __restrict__ src, const int* __restrict__ dst,
                            int* __restrict__ cur, int* __restrict__ esrc) {
    int e = blockIdx.x * blockDim.x + threadIdx.x;
    if (e < N_EDGES) {
        int pos = atomicAdd(&cur[dst[e]], 1);
        esrc[pos] = src[e];
    }
}

// ---------------- gather embedding (writes fp32 + bf16 shadow) ----------------
__global__ void gather_kernel(const float* __restrict__ embed,
                              const int* __restrict__ nodes,
                              float* __restrict__ h0,
                              __nv_bfloat16* __restrict__ hb0) {
    int t = blockIdx.x * blockDim.x + threadIdx.x;
    int v = t >> 5, l = t & 31;
    if (v < N_NODES) {
        int s = nodes[v];
        float4 x = reinterpret_cast<const float4*>(embed)[s * 32 + l];
        reinterpret_cast<float4*>(h0)[v * 32 + l] = x;
        uint2 b;
        b.x = pack_bf16x2(x.x, x.y);
        b.y = pack_bf16x2(x.z, x.w);
        reinterpret_cast<uint2*>(hb0)[v * 32 + l] = b;
    }
}

// ---------------- CSR mean aggregation: bf16 gather, fp32 accumulate ----------------
__global__ void agg_kernel(const __nv_bfloat16* __restrict__ hb,
                           const int* __restrict__ esrc,
                           const int* __restrict__ off,
                           float* __restrict__ mean) {
    int t = blockIdx.x * blockDim.x + threadIdx.x;
    int v = t >> 5, l = t & 31;
    if (v >= N_NODES) return;
    int beg = off[v];
    int end = off[v + 1];
    const uint2* hb2 = reinterpret_cast<const uint2*>(hb);   // 4 bf16 per uint2
    float ax = 0.f, ay = 0.f, az = 0.f, aw = 0.f;
    int j = beg;
    for (; j + 4 <= end; j += 4) {
        int s0 = esrc[j], s1 = esrc[j + 1], s2 = esrc[j + 2], s3 = esrc[j + 3];
        uint2 d0 = hb2[s0 * 32 + l];
        uint2 d1 = hb2[s1 * 32 + l];
        uint2 d2 = hb2[s2 * 32 + l];
        uint2 d3 = hb2[s3 * 32 + l];
        float2 f0a = __bfloat1622float2(*reinterpret_cast<__nv_bfloat162*>(&d0.x));
        float2 f0b = __bfloat1622float2(*reinterpret_cast<__nv_bfloat162*>(&d0.y));
        float2 f1a = __bfloat1622float2(*reinterpret_cast<__nv_bfloat162*>(&d1.x));
        float2 f1b = __bfloat1622float2(*reinterpret_cast<__nv_bfloat162*>(&d1.y));
        float2 f2a = __bfloat1622float2(*reinterpret_cast<__nv_bfloat162*>(&d2.x));
        float2 f2b = __bfloat1622float2(*reinterpret_cast<__nv_bfloat162*>(&d2.y));
        float2 f3a = __bfloat1622float2(*reinterpret_cast<__nv_bfloat162*>(&d3.x));
        float2 f3b = __bfloat1622float2(*reinterpret_cast<__nv_bfloat162*>(&d3.y));
        ax += (f0a.x + f1a.x) + (f2a.x + f3a.x);
        ay += (f0a.y + f1a.y) + (f2a.y + f3a.y);
        az += (f0b.x + f1b.x) + (f2b.x + f3b.x);
        aw += (f0b.y + f1b.y) + (f2b.y + f3b.y);
    }
    for (; j < end; j++) {
        uint2 d = hb2[esrc[j] * 32 + l];
        float2 fa = __bfloat1622float2(*reinterpret_cast<__nv_bfloat162*>(&d.x));
        float2 fb = __bfloat1622float2(*reinterpret_cast<__nv_bfloat162*>(&d.y));
        ax += fa.x; ay += fa.y; az += fb.x; aw += fb.y;
    }
    float invd = 1.0f / fmaxf((float)(end - beg), 1.0f);
    float4 r = make_float4(ax * invd, ay * invd, az * invd, aw * invd);
    reinterpret_cast<float4*>(mean)[v * 32 + l] = r;
}

// ---------------- mma.sync dual GEMM (bf16 hi/lo split -> fp32 accuracy) ----------------
// out[v,:] = mean[v] @ Wn + h[v] @ Ws + b  (optional ReLU). WB: also write bf16 shadow.
template <int BN, int NOUT, bool RELU, bool WB>
__global__ void __launch_bounds__(256) gemm_mma(
    const float* __restrict__ h, const float* __restrict__ mean,
    const float* __restrict__ Wn, const float* __restrict__ Ws,
    const float* __restrict__ bias, float* __restrict__ out,
    __nv_bfloat16* __restrict__ outb) {
    extern __shared__ char smem[];
    const uint32_t sb = smem_u32(smem);
    const int tid = threadIdx.x;
    const int wid = tid >> 5;
    const int lane = tid & 31;
    const int wm = wid >> 1;        // 0..3 (32 rows each)
    const int wn = wid & 1;         // 0..1 (BN/2 cols each)
    const int r0 = blockIdx.x * 128;

    constexpr int HN = BN / 2;
    constexpr int NT = HN / 8;
    constexpr uint32_t A_HI = 1024;
    constexpr uint32_t A_LO = 1024 + 16384;
    constexpr uint32_t B_HI = 1024 + 32768;
    constexpr uint32_t B_LO = B_HI + (uint32_t)BN * 128;

    if (tid < NOUT) *reinterpret_cast<float*>(smem + tid * 4) = bias[tid];

    const float4* mean4 = reinterpret_cast<const float4*>(mean);
    const float4* h4 = reinterpret_cast<const float4*>(h);

    float acc[2][NT][4];
#pragma unroll
    for (int i = 0; i < 2; i++)
#pragma unroll
        for (int j = 0; j < NT; j++)
#pragma unroll
            for (int q = 0; q < 4; q++) acc[i][j][q] = 0.f;

    for (int c = 0; c < 4; c++) {
        __syncthreads();

        // ---- A chunk: 128 rows x 64 floats -> bf16 hi/lo ----
#pragma unroll
        for (int it = 0; it < 8; it++) {
            int idx = tid + it * 256;
            int m = idx >> 4;
            int q = idx & 15;
            int row = r0 + m;
            float4 v = make_float4(0.f, 0.f, 0.f, 0.f);
            if (row < N_NODES)
                v = (c < 2) ? mean4[row * 32 + c * 16 + q]
                            : h4[row * 32 + (c - 2) * 16 + q];
            __nv_bfloat16 h0b, h1b, h2b, h3b, l0b, l1b, l2b, l3b;
            split_bf(v.x, h0b, l0b);
            split_bf(v.y, h1b, l1b);
            split_bf(v.z, h2b, l2b);
            split_bf(v.w, h3b, l3b);
            uint32_t off = (uint32_t)(m * 128 + q * 8);
            off ^= (uint32_t)(m & 7) << 4;
            __nv_bfloat162 hh0 = __halves2bfloat162(h0b, h1b);
            __nv_bfloat162 hh1 = __halves2bfloat162(h2b, h3b);
            __nv_bfloat162 ll0 = __halves2bfloat162(l0b, l1b);
            __nv_bfloat162 ll1 = __halves2bfloat162(l2b, l3b);
            *reinterpret_cast<uint2*>(smem + A_HI + off) =
                make_uint2(*reinterpret_cast<uint32_t*>(&hh0), *reinterpret_cast<uint32_t*>(&hh1));
            *reinterpret_cast<uint2*>(smem + A_LO + off) =
                make_uint2(*reinterpret_cast<uint32_t*>(&ll0), *reinterpret_cast<uint32_t*>(&ll1));
        }

        // ---- B chunk: 64 k-rows x BN cols of W ----
        {
            const float* W = (c < 2) ? Wn : Ws;
            int kb = (c & 1) * 64;
            if (BN == 128 && NOUT == 128) {
                const float4* W4 = reinterpret_cast<const float4*>(W);
#pragma unroll
                for (int it = 0; it < 8; it++) {
                    int idx = tid + it * 256;
                    int k = idx >> 5;
                    int nq = idx & 31;
                    float4 v = W4[(kb + k) * 32 + nq];
                    __nv_bfloat16 h0b, h1b, h2b, h3b, l0b, l1b, l2b, l3b;
                    split_bf(v.x, h0b, l0b);
                    split_bf(v.y, h1b, l1b);
                    split_bf(v.z, h2b, l2b);
                    split_bf(v.w, h3b, l3b);
                    uint32_t off = (uint32_t)(k * 256 + nq * 8);
                    off ^= (uint32_t)(k & 7) << 4;
                    __nv_bfloat162 hh0 = __halves2bfloat162(h0b, h1b);
                    __nv_bfloat162 hh1 = __halves2bfloat162(h2b, h3b);
                    __nv_bfloat162 ll0 = __halves2bfloat162(l0b, l1b);
                    __nv_bfloat162 ll1 = __halves2bfloat162(l2b, l3b);
                    *reinterpret_cast<uint2*>(smem + B_HI + off) =
                        make_uint2(*reinterpret_cast<uint32_t*>(&hh0), *reinterpret_cast<uint32_t*>(&hh1));
                    *reinterpret_cast<uint2*>(smem + B_LO + off) =
                        make_uint2(*reinterpret_cast<uint32_t*>(&ll0), *reinterpret_cast<uint32_t*>(&ll1));
                }
            } else {
#pragma unroll
                for (int it = 0; it < BN * 64 / 256; it++) {
                    int idx = tid + it * 256;
                    int k = idx / BN;
                    int n = idx % BN;
                    float w = (n < NOUT) ? W[(kb + k) * NOUT + n] : 0.f;
                    __nv_bfloat16 hi, lo;
                    split_bf(w, hi, lo);
                    uint32_t off = (uint32_t)(k * BN * 2 + n * 2);
                    off ^= (uint32_t)(k & 7) << 4;
                    *reinterpret_cast<__nv_bfloat16*>(smem + B_HI + off) = hi;
                    *reinterpret_cast<__nv_bfloat16*>(smem + B_LO + off) = lo;
                }
            }
        }
        __syncthreads();

        // ---- compute: 4 k-steps of 16 ----
#pragma unroll
        for (int kt = 0; kt < 4; kt++) {
            uint32_t ah[2][4], al[2][4];
            int arow_base = wm * 32 + (lane & 15);
            int akb = kt * 32 + ((lane >> 4) << 4);
#pragma unroll
            for (int mt = 0; mt < 2; mt++) {
                int row = arow_base + mt * 16;
                uint32_t off = (uint32_t)(row * 128 + akb);
                off ^= (uint32_t)(row & 7) << 4;
                ldsm4(ah[mt], sb + A_HI + off);
                ldsm4(al[mt], sb + A_LO + off);
            }
            int bk = kt * 16 + (lane & 15);
#pragma unroll
            for (int np = 0; np < NT / 2; np++) {
                int n0 = wn * HN + np * 16 + ((lane >> 4) << 3);
                uint32_t off = (uint32_t)(bk * BN * 2 + n0 * 2);
                off ^= (uint32_t)(bk & 7) << 4;
                uint32_t bh[4], bl[4];
                ldsm4t(bh, sb + B_HI + off);
                ldsm4t(bl, sb + B_LO + off);
#pragma unroll
                for (int hh = 0; hh < 2; hh++) {
                    int nt = np * 2 + hh;
#pragma unroll
                    for (int mt = 0; mt < 2; mt++) {
                        mma_bf16(acc[mt][nt], ah[mt], bh + 2 * hh);
                        mma_bf16(acc[mt][nt], ah[mt], bl + 2 * hh);
                        mma_bf16(acc[mt][nt], al[mt], bh + 2 * hh);
                    }
                }
            }
        }
    }

    // ---- epilogue ----
    const float* biasS = reinterpret_cast<const float*>(smem);
#pragma unroll
    for (int mt = 0; mt < 2; mt++) {
        int row = r0 + wm * 32 + mt * 16 + (lane >> 2);
#pragma unroll
        for (int nt = 0; nt < NT; nt++) {
            int col = wn * HN + nt * 8 + (lane & 3) * 2;
#pragma unroll
            for (int p = 0; p < 2; p++) {
                int r = row + p * 8;
                if (r < N_NODES) {
                    float v0 = acc[mt][nt][2 * p + 0];
                    float v1 = acc[mt][nt][2 * p + 1];
                    if (WB) {
                        // NOUT==128 here: both cols valid
                        float w0 = v0 + biasS[col];
                        float w1 = v1 + biasS[col + 1];
                        if (RELU) { w0 = fmaxf(w0, 0.f); w1 = fmaxf(w1, 0.f); }
                        reinterpret_cast<float2*>(out)[((size_t)r * NOUT + col) >> 1] =
                            make_float2(w0, w1);
                        reinterpret_cast<uint32_t*>(outb)[((size_t)r * NOUT + col) >> 1] =
                            pack_bf16x2(w0, w1);
                    } else {
                        if (col < NOUT) {
                            float v = v0 + biasS[col];
                            if (RELU) v = fmaxf(v, 0.f);
                            out[(size_t)r * NOUT + col] = v;
                        }
                        if (col + 1 < NOUT) {
                            float v = v1 + biasS[col + 1];
                            if (RELU) v = fmaxf(v, 0.f);
                            out[(size_t)r * NOUT + col + 1] = v;
                        }
                    }
                }
            }
        }
    }
}

// ---------------- launch ----------------
extern "C" void kernel_launch(void* const* d_in, const int* in_sizes, int n_in,
                              void* d_out, int out_size) {
    const float* embed  = (const float*)d_in[0];
    const float* Wself0 = (const float*)d_in[1];
    const float* Wneigh0= (const float*)d_in[2];
    const float* b0     = (const float*)d_in[3];
    const float* Wself1 = (const float*)d_in[4];
    const float* Wneigh1= (const float*)d_in[5];
    const float* b1     = (const float*)d_in[6];
    const float* Wself2 = (const float*)d_in[7];
    const float* Wneigh2= (const float*)d_in[8];
    const float* b2     = (const float*)d_in[9];
    const int* input_nodes = (const int*)d_in[10];
    const int* src      = (const int*)d_in[11];
    const int* dst      = (const int*)d_in[12];
    float* out = (float*)d_out;

    float *h0, *h1, *mean;
    __nv_bfloat16 *hb0, *hb1;
    int *cnt, *off, *cur, *esrc, *blksum;
    cudaGetSymbolAddress((void**)&h0, g_h0);
    cudaGetSymbolAddress((void**)&h1, g_h1);
    cudaGetSymbolAddress((void**)&mean, g_mean);
    cudaGetSymbolAddress((void**)&hb0, g_hb0);
    cudaGetSymbolAddress((void**)&hb1, g_hb1);
    cudaGetSymbolAddress((void**)&cnt, g_cnt);
    cudaGetSymbolAddress((void**)&off, g_off);
    cudaGetSymbolAddress((void**)&cur, g_cur);
    cudaGetSymbolAddress((void**)&esrc, g_esrc);
    cudaGetSymbolAddress((void**)&blksum, g_blksum);

    const int T = 256;
    const int gemm_blocks = (N_NODES + 127) / 128;           // 782
    const int warp_blocks = (N_NODES * 32 + T - 1) / T;

    const int SMEM_128 = 1024 + 32768 + 2 * 128 * 128;       // 66560
    const int SMEM_64  = 1024 + 32768 + 2 * 64 * 128;        // 50176
    cudaFuncSetAttribute(gemm_mma<128, 128, true, true>,
                         cudaFuncAttributeMaxDynamicSharedMemorySize, SMEM_128);
    cudaFuncSetAttribute(gemm_mma<64, NCLS, false, false>,
                         cudaFuncAttributeMaxDynamicSharedMemorySize, SMEM_64);

    // ---- CSR build (once; reused by all 3 layers) ----
    zero_int<<<(N_NODES + T - 1) / T, T>>>(cnt, N_NODES);
    hist_kernel<<<(N_EDGES + T - 1) / T, T>>>(dst, cnt);
    scan1_kernel<<<N_SCAN_BLKS, SCAN_BLK>>>(cnt, off, blksum);
    scan2_kernel<<<1, 128>>>(blksum);
    scan3_kernel<<<(N_NODES + T - 1) / T, T>>>(off, blksum, cur);
    fill_kernel<<<(N_EDGES + T - 1) / T, T>>>(src, dst, cur, esrc);

    // ---- embedding gather ----
    gather_kernel<<<warp_blocks, T>>>(embed, input_nodes, h0, hb0);

    // layer 0: h0 -> h1 (relu)
    agg_kernel<<<warp_blocks, T>>>(hb0, esrc, off, mean);
    gemm_mma<128, 128, true, true><<<gemm_blocks, T, SMEM_128>>>(
        h0, mean, Wneigh0, Wself0, b0, h1, hb1);

    // layer 1: h1 -> h0 (relu)
    agg_kernel<<<warp_blocks, T>>>(hb1, esrc, off, mean);
    gemm_mma<128, 128, true, true><<<gemm_blocks, T, SMEM_128>>>(
        h1, mean, Wneigh1, Wself1, b1, h0, hb0);

    // layer 2: h0 -> out (no relu, 47 classes)
    agg_kernel<<<warp_blocks, T>>>(hb0, esrc, off, mean);
    gemm_mma<64, NCLS, false, false><<<gemm_blocks, T, SMEM_64>>>(
        h0, mean, Wneigh2, Wself2, b2, out, nullptr);
}